// round 5
// baseline (speedup 1.0000x reference)
#include <cuda_runtime.h>

#define C_ATOM 128
#define C_REF  389
#define C_PAIR 16
#define CL_ROWS 16                 // rows per cl block (8 warps x 2 rows)
#define SCAN_ITERS 16              // pairs per thread in scan blocks

// ---------------------------------------------------------------------------
// Fused kernel launched AFTER cudaMemsetAsync zeroed the plm region.
//
// Blocks [0, clBlocks):  cl = feats @ W_feats + b_feats   (same as R3)
// Blocks [clBlocks, ..): scan uid pairs; for the ~0.4% matching pairs,
//                        compute the 16-wide affine row and scatter it.
//                        Zero pairs are already handled by the memset.
// ---------------------------------------------------------------------------
__global__ void __launch_bounds__(256)
fused_kernel(const float* __restrict__ pos,
             const float* __restrict__ charge,
             const float* __restrict__ mask,
             const float* __restrict__ elem,
             const float* __restrict__ names,
             const int*   __restrict__ uid,
             const float* __restrict__ Wf,
             const float* __restrict__ bf,
             const float* __restrict__ Woff,
             const float* __restrict__ boff,
             const float* __restrict__ Winv,
             const float* __restrict__ binv,
             const float* __restrict__ Wvm,
             const float* __restrict__ bvm,
             float* __restrict__ out, int N, int clBlocks)
{
    __shared__ float sf[CL_ROWS][C_REF];

    const int tid = threadIdx.x;

    if (blockIdx.x < clBlocks) {
        // ------------------------- cl path ---------------------------------
        const int n0   = blockIdx.x * CL_ROWS;
        const int warp = tid >> 5;
        const int lane = tid & 31;

        for (int idx = tid; idx < CL_ROWS * C_REF; idx += 256) {
            int r = idx / C_REF;
            int j = idx - r * C_REF;
            int n = n0 + r;
            float v;
            if (j < 3)        v = pos[n * 3 + j];
            else if (j == 3)  v = charge[n];
            else if (j == 4)  v = mask[n];
            else if (j < 133) v = elem[n * 128 + (j - 5)];
            else              v = names[n * 256 + (j - 133)];
            sf[r][j] = v;
        }
        __syncthreads();

        const int r0 = warp * 2;
        const int r1 = r0 + 1;
        const int c4 = lane * 4;

        float4 bias = *reinterpret_cast<const float4*>(bf + c4);
        float4 a0 = bias, a1 = bias;

#pragma unroll 4
        for (int j = 0; j < C_REF; j++) {
            float4 w = *reinterpret_cast<const float4*>(Wf + j * C_ATOM + c4);
            float f0 = sf[r0][j];
            float f1 = sf[r1][j];
            a0.x = fmaf(w.x, f0, a0.x); a0.y = fmaf(w.y, f0, a0.y);
            a0.z = fmaf(w.z, f0, a0.z); a0.w = fmaf(w.w, f0, a0.w);
            a1.x = fmaf(w.x, f1, a1.x); a1.y = fmaf(w.y, f1, a1.y);
            a1.z = fmaf(w.z, f1, a1.z); a1.w = fmaf(w.w, f1, a1.w);
        }

        *reinterpret_cast<float4*>(out + (long long)(n0 + r0) * C_ATOM + c4) = a0;
        *reinterpret_cast<float4*>(out + (long long)(n0 + r1) * C_ATOM + c4) = a1;
        return;
    }

    // --------------------------- scan/scatter path --------------------------
    const int sb = blockIdx.x - clBlocks;
    const long long base = (long long)sb * (256 * SCAN_ITERS);

    // Track (l, m) incrementally; p advances by 256 per iteration.
    int l     = (int)(base / N);
    int mBase = (int)(base - (long long)l * N);

    float* plm = out + (long long)N * C_ATOM;

#pragma unroll 4
    for (int it = 0; it < SCAN_ITERS; it++) {
        int m  = mBase + tid;
        int lt = l;
        if (m >= N) { m -= N; lt++; }   // warp-boundary wrap (predicated)

        const int um = __ldg(uid + m);
        const int ul = __ldg(uid + lt);

        if (um == ul) {
            // Rare (~0.4%): compute the 16-wide affine row and write 64B.
            const float d0 = __ldg(pos + lt * 3 + 0) - __ldg(pos + m * 3 + 0);
            const float d1 = __ldg(pos + lt * 3 + 1) - __ldg(pos + m * 3 + 1);
            const float d2 = __ldg(pos + lt * 3 + 2) - __ldg(pos + m * 3 + 2);
            float s = fmaf(d0, d0, 1.0f);
            s = fmaf(d1, d1, s);
            s = fmaf(d2, d2, s);
            const float inv = __fdividef(1.0f, s);

            float* op = plm + ((long long)lt * N + m) * C_PAIR;
#pragma unroll
            for (int kg = 0; kg < C_PAIR; kg += 4) {
                const float4 w0 = *reinterpret_cast<const float4*>(Woff + kg);
                const float4 w1 = *reinterpret_cast<const float4*>(Woff + C_PAIR + kg);
                const float4 w2 = *reinterpret_cast<const float4*>(Woff + 2 * C_PAIR + kg);
                const float4 wi = *reinterpret_cast<const float4*>(Winv + kg);
                const float4 t1 = *reinterpret_cast<const float4*>(boff + kg);
                const float4 t2 = *reinterpret_cast<const float4*>(binv + kg);
                const float4 t3 = *reinterpret_cast<const float4*>(Wvm + kg);
                const float4 t4 = *reinterpret_cast<const float4*>(bvm + kg);

                float4 r;
                r.x = t1.x + t2.x + t3.x + t4.x;
                r.y = t1.y + t2.y + t3.y + t4.y;
                r.z = t1.z + t2.z + t3.z + t4.z;
                r.w = t1.w + t2.w + t3.w + t4.w;
                r.x = fmaf(d0, w0.x, r.x);  r.y = fmaf(d0, w0.y, r.y);
                r.z = fmaf(d0, w0.z, r.z);  r.w = fmaf(d0, w0.w, r.w);
                r.x = fmaf(d1, w1.x, r.x);  r.y = fmaf(d1, w1.y, r.y);
                r.z = fmaf(d1, w1.z, r.z);  r.w = fmaf(d1, w1.w, r.w);
                r.x = fmaf(d2, w2.x, r.x);  r.y = fmaf(d2, w2.y, r.y);
                r.z = fmaf(d2, w2.z, r.z);  r.w = fmaf(d2, w2.w, r.w);
                r.x = fmaf(inv, wi.x, r.x); r.y = fmaf(inv, wi.y, r.y);
                r.z = fmaf(inv, wi.z, r.z); r.w = fmaf(inv, wi.w, r.w);

                *reinterpret_cast<float4*>(op + kg) = r;
            }
        }

        mBase += 256;
        if (mBase >= N) { mBase -= N; l++; }
    }
}

// ---------------------------------------------------------------------------
// Launch: memset zeroes the plm region (pure write stream at near-peak BW),
// then one fused kernel fills cl and the sparse nonzero plm entries.
// ---------------------------------------------------------------------------
extern "C" void kernel_launch(void* const* d_in, const int* in_sizes, int n_in,
                              void* d_out, int out_size)
{
    const float* pos    = (const float*)d_in[0];
    const float* charge = (const float*)d_in[1];
    const float* maskp  = (const float*)d_in[2];
    const float* elem   = (const float*)d_in[3];
    const float* names  = (const float*)d_in[4];
    const int*   uid    = (const int*)  d_in[5];
    const float* Wf     = (const float*)d_in[6];
    const float* bf     = (const float*)d_in[7];
    const float* Woff   = (const float*)d_in[8];
    const float* boff   = (const float*)d_in[9];
    const float* Winv   = (const float*)d_in[10];
    const float* binv   = (const float*)d_in[11];
    const float* Wvm    = (const float*)d_in[12];
    const float* bvm    = (const float*)d_in[13];

    const int N = in_sizes[1];  // B*N with B=1
    float* out = (float*)d_out;

    // Zero the plm region with the driver's pure-write path.
    const size_t plmBytes = (size_t)N * N * C_PAIR * sizeof(float);
    cudaMemsetAsync(out + (long long)N * C_ATOM, 0, plmBytes);

    const int clBlocks = N / CL_ROWS;  // 128
    const long long pairs = (long long)N * N;
    const int scanBlocks = (int)(pairs / (256 * SCAN_ITERS));  // 1024

    fused_kernel<<<clBlocks + scanBlocks, 256>>>(
        pos, charge, maskp, elem, names, uid, Wf, bf,
        Woff, boff, Winv, binv, Wvm, bvm, out, N, clBlocks);
}

// round 6
// speedup vs baseline: 1.1398x; 1.1398x over previous
#include <cuda_runtime.h>

#define C_ATOM 128
#define C_REF  389
#define C_PAIR 16
#define CL_ROWS 16      // rows per cl block (8 warps x 2 rows)

// ---------------------------------------------------------------------------
// Fused kernel (single launch).
// Blocks [0, clBlocks):        cl = feats @ W_feats + b_feats
// Blocks [clBlocks, +N):       plm row l = blockIdx.x - clBlocks.
//   256 threads, 2 threads per pair, each stores 32B via st.global.v8.f32
//   -> warp store = 1024B contiguous. 16 iters cover all N=2048 m.
//   v = (uid[l]==uid[m]) is 0 for ~99.6% of pairs: zero path touches only
//   uid (L1-resident 8KB) and the store pipe. Match path computes the
//   8 channels this thread owns, loading coefficients ad hoc (L1-hot).
// ---------------------------------------------------------------------------
__global__ void __launch_bounds__(256)
fused_kernel(const float* __restrict__ pos,
             const float* __restrict__ charge,
             const float* __restrict__ mask,
             const float* __restrict__ elem,
             const float* __restrict__ names,
             const int*   __restrict__ uid,
             const float* __restrict__ Wf,
             const float* __restrict__ bf,
             const float* __restrict__ Woff,
             const float* __restrict__ boff,
             const float* __restrict__ Winv,
             const float* __restrict__ binv,
             const float* __restrict__ Wvm,
             const float* __restrict__ bvm,
             float* __restrict__ out, int N, int clBlocks)
{
    __shared__ float sf[CL_ROWS][C_REF];

    const int tid = threadIdx.x;

    if (blockIdx.x < clBlocks) {
        // ------------------------- cl path ---------------------------------
        const int n0   = blockIdx.x * CL_ROWS;
        const int warp = tid >> 5;
        const int lane = tid & 31;

        for (int idx = tid; idx < CL_ROWS * C_REF; idx += 256) {
            int r = idx / C_REF;
            int j = idx - r * C_REF;
            int n = n0 + r;
            float v;
            if (j < 3)        v = pos[n * 3 + j];
            else if (j == 3)  v = charge[n];
            else if (j == 4)  v = mask[n];
            else if (j < 133) v = elem[n * 128 + (j - 5)];
            else              v = names[n * 256 + (j - 133)];
            sf[r][j] = v;
        }
        __syncthreads();

        const int r0 = warp * 2;
        const int r1 = r0 + 1;
        const int c4 = lane * 4;

        float4 bias = *reinterpret_cast<const float4*>(bf + c4);
        float4 a0 = bias, a1 = bias;

#pragma unroll 4
        for (int j = 0; j < C_REF; j++) {
            float4 w = *reinterpret_cast<const float4*>(Wf + j * C_ATOM + c4);
            float f0 = sf[r0][j];
            float f1 = sf[r1][j];
            a0.x = fmaf(w.x, f0, a0.x); a0.y = fmaf(w.y, f0, a0.y);
            a0.z = fmaf(w.z, f0, a0.z); a0.w = fmaf(w.w, f0, a0.w);
            a1.x = fmaf(w.x, f1, a1.x); a1.y = fmaf(w.y, f1, a1.y);
            a1.z = fmaf(w.z, f1, a1.z); a1.w = fmaf(w.w, f1, a1.w);
        }

        *reinterpret_cast<float4*>(out + (long long)(n0 + r0) * C_ATOM + c4) = a0;
        *reinterpret_cast<float4*>(out + (long long)(n0 + r1) * C_ATOM + c4) = a1;
        return;
    }

    // --------------------------- plm path ----------------------------------
    const int l    = blockIdx.x - clBlocks;   // one l per block
    const int pair = tid >> 1;                // 0..127 within each iter
    const int kg0  = (tid & 1) * 8;           // channel base: 0 or 8

    const int ul = __ldg(uid + l);

    int m = pair;
    float* op = out + (long long)N * C_ATOM
                    + ((long long)l * N + pair) * C_PAIR + kg0;

    const int iters = N >> 7;                 // 128 pairs per iteration

#pragma unroll 4
    for (int it = 0; it < iters; it++) {
        const int um = __ldg(uid + m);

        float r0 = 0.f, r1 = 0.f, r2 = 0.f, r3 = 0.f;
        float r4 = 0.f, r5 = 0.f, r6 = 0.f, r7 = 0.f;

        if (um == ul) {
            // Rare (~0.4%): full affine map for the 8 channels this thread owns.
            const float d0 = __ldg(pos + l * 3 + 0) - __ldg(pos + m * 3 + 0);
            const float d1 = __ldg(pos + l * 3 + 1) - __ldg(pos + m * 3 + 1);
            const float d2 = __ldg(pos + l * 3 + 2) - __ldg(pos + m * 3 + 2);
            float s = fmaf(d0, d0, 1.0f);
            s = fmaf(d1, d1, s);
            s = fmaf(d2, d2, s);
            const float inv = __fdividef(1.0f, s);

            float acc[8];
#pragma unroll
            for (int q = 0; q < 8; q++) {
                const int c = kg0 + q;
                float t = __ldg(boff + c) + __ldg(binv + c)
                        + __ldg(Wvm + c) + __ldg(bvm + c);
                t = fmaf(d0, __ldg(Woff + c),             t);
                t = fmaf(d1, __ldg(Woff + C_PAIR + c),    t);
                t = fmaf(d2, __ldg(Woff + 2 * C_PAIR + c), t);
                t = fmaf(inv, __ldg(Winv + c),            t);
                acc[q] = t;
            }
            r0 = acc[0]; r1 = acc[1]; r2 = acc[2]; r3 = acc[3];
            r4 = acc[4]; r5 = acc[5]; r6 = acc[6]; r7 = acc[7];
        }

        // 256-bit streaming store: 32B per thread, 1024B per warp instruction.
        asm volatile(
            "st.global.cs.v8.f32 [%0], {%1, %2, %3, %4, %5, %6, %7, %8};"
            :: "l"(op), "f"(r0), "f"(r1), "f"(r2), "f"(r3),
               "f"(r4), "f"(r5), "f"(r6), "f"(r7)
            : "memory");

        m  += 128;
        op += 128 * C_PAIR;
    }
}

// ---------------------------------------------------------------------------
// Launch: one kernel. cl blocks first (long-latency, start early), then one
// plm block per output row l.
// ---------------------------------------------------------------------------
extern "C" void kernel_launch(void* const* d_in, const int* in_sizes, int n_in,
                              void* d_out, int out_size)
{
    const float* pos    = (const float*)d_in[0];
    const float* charge = (const float*)d_in[1];
    const float* maskp  = (const float*)d_in[2];
    const float* elem   = (const float*)d_in[3];
    const float* names  = (const float*)d_in[4];
    const int*   uid    = (const int*)  d_in[5];
    const float* Wf     = (const float*)d_in[6];
    const float* bf     = (const float*)d_in[7];
    const float* Woff   = (const float*)d_in[8];
    const float* boff   = (const float*)d_in[9];
    const float* Winv   = (const float*)d_in[10];
    const float* binv   = (const float*)d_in[11];
    const float* Wvm    = (const float*)d_in[12];
    const float* bvm    = (const float*)d_in[13];

    const int N = in_sizes[1];  // B*N with B=1
    float* out = (float*)d_out;

    const int clBlocks = N / CL_ROWS;   // 128
    fused_kernel<<<clBlocks + N, 256>>>(
        pos, charge, maskp, elem, names, uid, Wf, bf,
        Woff, boff, Winv, binv, Wvm, bvm, out, N, clBlocks);
}

// round 7
// speedup vs baseline: 1.6831x; 1.4767x over previous
#include <cuda_runtime.h>

#define C_ATOM 128
#define C_REF  389
#define C_PAIR 16
#define CL_ROWS 8          // rows per cl block (8 warps x 1 row)
#define PLM_ITERS 16       // 64 pairs/iter * 16 = 1024 pairs/block

// ---------------------------------------------------------------------------
// Fused kernel, tuned for maximum resident store concurrency (8 blocks/SM).
//
// Blocks [0, clBlocks):  cl = feats @ W_feats + b_feats.
//   8 warps x 1 row; lane owns 4 channels (LDG.128 on W, 512B/warp).
// Blocks [clBlocks, +N*N/1024): plm.
//   4 threads/pair, float4 streaming stores (512B/warp instr).
//   Zero path (~99.6%): LDG uid -> ISETP -> STG.cs.128. Coefficients are
//   loaded only inside the rare match branch to keep zero-path regs ~12.
// ---------------------------------------------------------------------------
__global__ void __launch_bounds__(256, 8)
fused_kernel(const float* __restrict__ pos,
             const float* __restrict__ charge,
             const float* __restrict__ mask,
             const float* __restrict__ elem,
             const float* __restrict__ names,
             const int*   __restrict__ uid,
             const float* __restrict__ Wf,
             const float* __restrict__ bf,
             const float* __restrict__ Woff,
             const float* __restrict__ boff,
             const float* __restrict__ Winv,
             const float* __restrict__ binv,
             const float* __restrict__ Wvm,
             const float* __restrict__ bvm,
             float* __restrict__ out, int N, int clBlocks)
{
    __shared__ float sf[CL_ROWS][C_REF];

    const int tid = threadIdx.x;

    if (blockIdx.x < clBlocks) {
        // ------------------------- cl path ---------------------------------
        const int n0   = blockIdx.x * CL_ROWS;
        const int warp = tid >> 5;
        const int lane = tid & 31;

        for (int idx = tid; idx < CL_ROWS * C_REF; idx += 256) {
            int r = idx / C_REF;
            int j = idx - r * C_REF;
            int n = n0 + r;
            float v;
            if (j < 3)        v = pos[n * 3 + j];
            else if (j == 3)  v = charge[n];
            else if (j == 4)  v = mask[n];
            else if (j < 133) v = elem[n * 128 + (j - 5)];
            else              v = names[n * 256 + (j - 133)];
            sf[r][j] = v;
        }
        __syncthreads();

        const int c4 = lane * 4;
        float4 acc = *reinterpret_cast<const float4*>(bf + c4);

#pragma unroll 4
        for (int j = 0; j < C_REF; j++) {
            float4 w = *reinterpret_cast<const float4*>(Wf + j * C_ATOM + c4);
            float  f = sf[warp][j];
            acc.x = fmaf(w.x, f, acc.x);
            acc.y = fmaf(w.y, f, acc.y);
            acc.z = fmaf(w.z, f, acc.z);
            acc.w = fmaf(w.w, f, acc.w);
        }
        *reinterpret_cast<float4*>(out + (long long)(n0 + warp) * C_ATOM + c4) = acc;
        return;
    }

    // --------------------------- plm path ----------------------------------
    const int pair = tid >> 2;           // 0..63
    const int kg   = (tid & 3) * 4;      // 0,4,8,12

    const long long pbase = (long long)(blockIdx.x - clBlocks) * (64 * PLM_ITERS);
    const int l = (int)(pbase / N);
    int m       = (int)(pbase - (long long)l * N) + pair;

    const int ul = __ldg(uid + l);

    float* op = out + (long long)N * C_ATOM + (pbase + pair) * C_PAIR + kg;

#pragma unroll 4
    for (int it = 0; it < PLM_ITERS; it++) {
        const int um = __ldg(uid + m);

        float4 r = make_float4(0.f, 0.f, 0.f, 0.f);

        if (um == ul) {
            // Rare (~0.4%): full affine map. All operand loads live here so
            // the dominant zero path stays register-minimal.
            const float d0 = __ldg(pos + l * 3 + 0) - __ldg(pos + m * 3 + 0);
            const float d1 = __ldg(pos + l * 3 + 1) - __ldg(pos + m * 3 + 1);
            const float d2 = __ldg(pos + l * 3 + 2) - __ldg(pos + m * 3 + 2);
            float s = fmaf(d0, d0, 1.0f);
            s = fmaf(d1, d1, s);
            s = fmaf(d2, d2, s);
            const float inv = __fdividef(1.0f, s);

#pragma unroll
            for (int q = 0; q < 4; q++) {
                const int c = kg + q;
                float t = __ldg(boff + c) + __ldg(binv + c)
                        + __ldg(Wvm + c) + __ldg(bvm + c);
                t = fmaf(d0,  __ldg(Woff + c),              t);
                t = fmaf(d1,  __ldg(Woff + C_PAIR + c),     t);
                t = fmaf(d2,  __ldg(Woff + 2 * C_PAIR + c), t);
                t = fmaf(inv, __ldg(Winv + c),              t);
                (&r.x)[q] = t;
            }
        }

        __stcs(reinterpret_cast<float4*>(op), r);

        m  += 64;
        op += 64 * C_PAIR;
    }
}

// ---------------------------------------------------------------------------
// Launch: single kernel; cl blocks first, then 4096 plm blocks.
// ---------------------------------------------------------------------------
extern "C" void kernel_launch(void* const* d_in, const int* in_sizes, int n_in,
                              void* d_out, int out_size)
{
    const float* pos    = (const float*)d_in[0];
    const float* charge = (const float*)d_in[1];
    const float* maskp  = (const float*)d_in[2];
    const float* elem   = (const float*)d_in[3];
    const float* names  = (const float*)d_in[4];
    const int*   uid    = (const int*)  d_in[5];
    const float* Wf     = (const float*)d_in[6];
    const float* bf     = (const float*)d_in[7];
    const float* Woff   = (const float*)d_in[8];
    const float* boff   = (const float*)d_in[9];
    const float* Winv   = (const float*)d_in[10];
    const float* binv   = (const float*)d_in[11];
    const float* Wvm    = (const float*)d_in[12];
    const float* bvm    = (const float*)d_in[13];

    const int N = in_sizes[1];  // B*N with B=1
    float* out = (float*)d_out;

    const int clBlocks = N / CL_ROWS;                           // 256
    const long long pairs = (long long)N * N;
    const unsigned int plmBlocks =
        (unsigned int)(pairs / (64 * PLM_ITERS));               // 4096

    fused_kernel<<<clBlocks + plmBlocks, 256>>>(
        pos, charge, maskp, elem, names, uid, Wf, bf,
        Woff, boff, Winv, binv, Wvm, bvm, out, N, clBlocks);
}

// round 8
// speedup vs baseline: 1.8145x; 1.0780x over previous
#include <cuda_runtime.h>

#define C_ATOM 128
#define C_REF  389
#define C_PAIR 16
#define CL_ROWS 8          // rows per cl block (8 warps x 1 row)
#define PLM_ITERS 8        // 64 pairs/iter * 8 = 512 pairs/block

// ---------------------------------------------------------------------------
// Fused kernel.
// Blocks [0, clBlocks):  cl = feats @ W_feats + b_feats (8 warps x 1 row).
// Blocks [clBlocks, ..): plm, 512 pairs/block, 4 threads/pair.
//   Phase A: 8 independent uid LDGs + 8 UNCONDITIONAL zero STG.cs.128
//            (no data/addr dependencies -> memset-rate store issue).
//   Phase B: rare (~0.4%) matching slots recomputed and re-stored by the
//            same thread (program order to same address -> correct final value).
// ---------------------------------------------------------------------------
__global__ void __launch_bounds__(256, 8)
fused_kernel(const float* __restrict__ pos,
             const float* __restrict__ charge,
             const float* __restrict__ mask,
             const float* __restrict__ elem,
             const float* __restrict__ names,
             const int*   __restrict__ uid,
             const float* __restrict__ Wf,
             const float* __restrict__ bf,
             const float* __restrict__ Woff,
             const float* __restrict__ boff,
             const float* __restrict__ Winv,
             const float* __restrict__ binv,
             const float* __restrict__ Wvm,
             const float* __restrict__ bvm,
             float* __restrict__ out, int N, int clBlocks)
{
    __shared__ float sf[CL_ROWS][C_REF];

    const int tid = threadIdx.x;

    if (blockIdx.x < clBlocks) {
        // ------------------------- cl path ---------------------------------
        const int n0   = blockIdx.x * CL_ROWS;
        const int warp = tid >> 5;
        const int lane = tid & 31;

        for (int idx = tid; idx < CL_ROWS * C_REF; idx += 256) {
            int r = idx / C_REF;
            int j = idx - r * C_REF;
            int n = n0 + r;
            float v;
            if (j < 3)        v = pos[n * 3 + j];
            else if (j == 3)  v = charge[n];
            else if (j == 4)  v = mask[n];
            else if (j < 133) v = elem[n * 128 + (j - 5)];
            else              v = names[n * 256 + (j - 133)];
            sf[r][j] = v;
        }
        __syncthreads();

        const int c4 = lane * 4;
        float4 acc = *reinterpret_cast<const float4*>(bf + c4);

#pragma unroll 4
        for (int j = 0; j < C_REF; j++) {
            float4 w = *reinterpret_cast<const float4*>(Wf + j * C_ATOM + c4);
            float  f = sf[warp][j];
            acc.x = fmaf(w.x, f, acc.x);
            acc.y = fmaf(w.y, f, acc.y);
            acc.z = fmaf(w.z, f, acc.z);
            acc.w = fmaf(w.w, f, acc.w);
        }
        *reinterpret_cast<float4*>(out + (long long)(n0 + warp) * C_ATOM + c4) = acc;
        return;
    }

    // --------------------------- plm path ----------------------------------
    const int pair = tid >> 2;           // 0..63
    const int kg   = (tid & 3) * 4;      // 0,4,8,12

    const long long pbase = (long long)(blockIdx.x - clBlocks) * (64 * PLM_ITERS);
    const int l  = (int)(pbase / N);
    const int m0 = (int)(pbase - (long long)l * N) + pair;

    const int ul = __ldg(uid + l);

    float* op = out + (long long)N * C_ATOM + (pbase + pair) * C_PAIR + kg;

    // Phase A: batch all uid loads (independent) ...
    int um[PLM_ITERS];
#pragma unroll
    for (int it = 0; it < PLM_ITERS; it++)
        um[it] = __ldg(uid + m0 + it * 64);

    // ... and all zero stores (no dependencies: pure store-issue stream).
    const float4 z = make_float4(0.f, 0.f, 0.f, 0.f);
#pragma unroll
    for (int it = 0; it < PLM_ITERS; it++)
        __stcs(reinterpret_cast<float4*>(op + (long long)it * (64 * C_PAIR)), z);

    // Phase B: rare overwrites (same thread, same address -> ordered).
#pragma unroll
    for (int it = 0; it < PLM_ITERS; it++) {
        if (um[it] == ul) {
            const int m = m0 + it * 64;
            const float d0 = __ldg(pos + l * 3 + 0) - __ldg(pos + m * 3 + 0);
            const float d1 = __ldg(pos + l * 3 + 1) - __ldg(pos + m * 3 + 1);
            const float d2 = __ldg(pos + l * 3 + 2) - __ldg(pos + m * 3 + 2);
            float s = fmaf(d0, d0, 1.0f);
            s = fmaf(d1, d1, s);
            s = fmaf(d2, d2, s);
            const float inv = __fdividef(1.0f, s);

            float4 r;
#pragma unroll
            for (int q = 0; q < 4; q++) {
                const int c = kg + q;
                float t = __ldg(boff + c) + __ldg(binv + c)
                        + __ldg(Wvm + c) + __ldg(bvm + c);
                t = fmaf(d0,  __ldg(Woff + c),              t);
                t = fmaf(d1,  __ldg(Woff + C_PAIR + c),     t);
                t = fmaf(d2,  __ldg(Woff + 2 * C_PAIR + c), t);
                t = fmaf(inv, __ldg(Winv + c),              t);
                (&r.x)[q] = t;
            }
            __stcs(reinterpret_cast<float4*>(op + (long long)it * (64 * C_PAIR)), r);
        }
    }
}

// ---------------------------------------------------------------------------
// Launch: single kernel; 256 cl blocks then 8192 plm blocks (~7 waves,
// small tail).
// ---------------------------------------------------------------------------
extern "C" void kernel_launch(void* const* d_in, const int* in_sizes, int n_in,
                              void* d_out, int out_size)
{
    const float* pos    = (const float*)d_in[0];
    const float* charge = (const float*)d_in[1];
    const float* maskp  = (const float*)d_in[2];
    const float* elem   = (const float*)d_in[3];
    const float* names  = (const float*)d_in[4];
    const int*   uid    = (const int*)  d_in[5];
    const float* Wf     = (const float*)d_in[6];
    const float* bf     = (const float*)d_in[7];
    const float* Woff   = (const float*)d_in[8];
    const float* boff   = (const float*)d_in[9];
    const float* Winv   = (const float*)d_in[10];
    const float* binv   = (const float*)d_in[11];
    const float* Wvm    = (const float*)d_in[12];
    const float* bvm    = (const float*)d_in[13];

    const int N = in_sizes[1];  // B*N with B=1
    float* out = (float*)d_out;

    const int clBlocks = N / CL_ROWS;                           // 256
    const long long pairs = (long long)N * N;
    const unsigned int plmBlocks =
        (unsigned int)(pairs / (64 * PLM_ITERS));               // 8192

    fused_kernel<<<clBlocks + plmBlocks, 256>>>(
        pos, charge, maskp, elem, names, uid, Wf, bf,
        Woff, boff, Winv, binv, Wvm, bvm, out, N, clBlocks);
}